// round 2
// baseline (speedup 1.0000x reference)
#include <cuda_runtime.h>
#include <cstdint>

#define N 8192
#define D 128
#define RB 32              // rows per CTA
#define CT 128             // cols per tile
#define CSPLIT 2           // column split across CTAs
#define CPC (N / CSPLIT)   // 4096 cols per CTA
#define NT (CPC / CT)      // 32 tiles
#define AST 68             // As2 row stride (floats): 2*RB dup + pad
#define BST 132            // Bs row stride (floats): CT + pad

__device__ float g_xT[D * N];              // transposed inputs [k][n]
__device__ float g_sq[N];
__device__ float g_topD[CSPLIT * N * 5];
__device__ int   g_topI[CSPLIT * N * 5];
__device__ float g_hinge[N];

__device__ __forceinline__ bool better(float d1, int i1, float d2, int i2) {
    return (d1 < d2) || (d1 == d2 && i1 < i2);
}

__device__ __forceinline__ void ffma2(uint64_t& d, uint64_t a, uint64_t b) {
    asm("fma.rn.f32x2 %0, %1, %2, %0;" : "+l"(d) : "l"(a), "l"(b));
}

__device__ __forceinline__ void unpack2(float& lo, float& hi, uint64_t v) {
    asm("mov.b64 {%0, %1}, %2;" : "=f"(lo), "=f"(hi) : "l"(v));
}

// ---------------------------------------------------------------------------
// Kernel T: transpose x[n][d] -> g_xT[d][n]
// ---------------------------------------------------------------------------
__global__ void transpose_kernel(const float* __restrict__ x) {
    __shared__ float t[32][33];
    int lx = threadIdx.x, ly = threadIdx.y;           // 32 x 8
    int n0 = blockIdx.x * 32, d0 = blockIdx.y * 32;
#pragma unroll
    for (int i = 0; i < 4; i++)
        t[ly + 8 * i][lx] = x[(n0 + ly + 8 * i) * D + d0 + lx];
    __syncthreads();
#pragma unroll
    for (int i = 0; i < 4; i++)
        g_xT[(d0 + ly + 8 * i) * N + n0 + lx] = t[lx][ly + 8 * i];
}

// ---------------------------------------------------------------------------
// Kernel A: row squared norms
// ---------------------------------------------------------------------------
__global__ void sq_kernel(const float* __restrict__ x) {
    int row  = blockIdx.x * 8 + (threadIdx.x >> 5);
    int lane = threadIdx.x & 31;
    const float* xr = x + row * D;
    float s = 0.f;
#pragma unroll
    for (int k = 0; k < 4; k++) {
        float v = xr[lane + 32 * k];
        s = fmaf(v, v, s);
    }
#pragma unroll
    for (int o = 16; o; o >>= 1) s += __shfl_xor_sync(0xffffffffu, s, o);
    if (lane == 0) g_sq[row] = s;
}

// ---------------------------------------------------------------------------
// Kernel B: fused Gram tile (packed f32x2 FMA) + per-row top-5.
// Grid (CSPLIT, N/RB), 256 threads as 16(tx) x 16(ty).
// Each thread: 2 rows x 8 cols micro-tile, accumulated as 2x4 f32x2 pairs.
// A tile stored VALUE-DUPLICATED in smem so LDS.128 yields packed (a,a).
// ---------------------------------------------------------------------------
extern __shared__ float smem[];

__global__ __launch_bounds__(256) void dist_top5_kernel() {
    float* As2 = smem;               // [D][AST]: As2[k][2r] = As2[k][2r+1] = x[rowBase+r][k]
    float* Bs  = smem + D * AST;     // [D][BST]: Bs[k][c] = x[colBase+c][k]

    const int bx = blockIdx.x;
    const int by = blockIdx.y;
    const int tid = threadIdx.x;
    const int tx = tid & 15;
    const int ty = tid >> 4;
    const int rowBase = by * RB;
    const int r0 = rowBase + ty * 2;

    // One-time A tile load from xT: coalesced LDG, duplicated STS.64
    {
        int r = tid & 31, k = tid >> 5;        // 4096 elems = 256 threads x 16
#pragma unroll
        for (int v = 0; v < 16; v++) {
            float val = g_xT[(k + 8 * v) * N + rowBase + r];
            *(float2*)&As2[(k + 8 * v) * AST + 2 * r] = make_float2(val, val);
        }
    }

    float sqR[2];
    sqR[0] = g_sq[r0];
    sqR[1] = g_sq[r0 + 1];

    float t5d[2][5];
    int   t5i[2][5];
#pragma unroll
    for (int r = 0; r < 2; r++)
#pragma unroll
        for (int s = 0; s < 5; s++) {
            t5d[r][s] = __int_as_float(0x7f800000);
            t5i[r][s] = 0x7fffffff;
        }

    for (int t = 0; t < NT; t++) {
        const int colBase = bx * CPC + t * CT;
        __syncthreads();
        // B tile load from xT: fully coalesced LDG.128 + conflict-free STS.128
        {
            int c4 = tid & 31, kb = tid >> 5;  // 4096 float4 = 256 threads x 16
#pragma unroll
            for (int v = 0; v < 16; v++) {
                int k = kb + 8 * v;
                float4 val = *(const float4*)&g_xT[k * N + colBase + c4 * 4];
                *(float4*)&Bs[k * BST + c4 * 4] = val;
            }
        }
        __syncthreads();

        uint64_t accp[2][4];
#pragma unroll
        for (int r = 0; r < 2; r++)
#pragma unroll
            for (int p = 0; p < 4; p++) accp[r][p] = 0ull;

#pragma unroll 8
        for (int k = 0; k < D; k++) {
            ulonglong2 aa = *(const ulonglong2*)&As2[k * AST + ty * 4]; // (a0,a0),(a1,a1)
            ulonglong2 b0 = *(const ulonglong2*)&Bs[k * BST + tx * 8];     // (b0,b1),(b2,b3)
            ulonglong2 b1 = *(const ulonglong2*)&Bs[k * BST + tx * 8 + 4]; // (b4,b5),(b6,b7)
            ffma2(accp[0][0], aa.x, b0.x);
            ffma2(accp[0][1], aa.x, b0.y);
            ffma2(accp[0][2], aa.x, b1.x);
            ffma2(accp[0][3], aa.x, b1.y);
            ffma2(accp[1][0], aa.y, b0.x);
            ffma2(accp[1][1], aa.y, b0.y);
            ffma2(accp[1][2], aa.y, b1.x);
            ffma2(accp[1][3], aa.y, b1.y);
        }

        // Candidate insertion (ascending j per thread -> stable tie handling)
#pragma unroll
        for (int p = 0; p < 4; p++) {
            int jBase = colBase + tx * 8 + 2 * p;
            float sq0 = g_sq[jBase];
            float sq1 = g_sq[jBase + 1];
#pragma unroll
            for (int r = 0; r < 2; r++) {
                float dot0, dot1;
                unpack2(dot0, dot1, accp[r][p]);
#pragma unroll
                for (int h = 0; h < 2; h++) {
                    int j = jBase + h;
                    float d2 = fmaf(-2.f, h ? dot1 : dot0, sqR[r] + (h ? sq1 : sq0));
                    d2 = fmaxf(d2, 1e-12f);
                    if (better(d2, j, t5d[r][4], t5i[r][4])) {
                        float cd = d2; int ci = j;
#pragma unroll
                        for (int s = 0; s < 5; s++) {
                            if (better(cd, ci, t5d[r][s], t5i[r][s])) {
                                float td = t5d[r][s]; t5d[r][s] = cd; cd = td;
                                int   ti = t5i[r][s]; t5i[r][s] = ci; ci = ti;
                            }
                        }
                    }
                }
            }
        }
    }

    // Butterfly merge across the 16 tx-threads (half-warp) of each row group
#pragma unroll
    for (int r = 0; r < 2; r++) {
#pragma unroll
        for (int off = 1; off < 16; off <<= 1) {
            float od[5]; int oi[5];
#pragma unroll
            for (int s = 0; s < 5; s++) {
                od[s] = __shfl_xor_sync(0xffffffffu, t5d[r][s], off);
                oi[s] = __shfl_xor_sync(0xffffffffu, t5i[r][s], off);
            }
            float ad[5]; int ai[5];
#pragma unroll
            for (int s = 0; s < 5; s++) { ad[s] = t5d[r][s]; ai[s] = t5i[r][s]; }
            int ia = 0, ib = 0;
#pragma unroll
            for (int s = 0; s < 5; s++) {
                bool ta = better(ad[ia], ai[ia], od[ib], oi[ib]);
                t5d[r][s] = ta ? ad[ia] : od[ib];
                t5i[r][s] = ta ? ai[ia] : oi[ib];
                if (ta) ia++; else ib++;
            }
        }
    }

    if (tx == 0) {
#pragma unroll
        for (int r = 0; r < 2; r++) {
            int row = r0 + r;
#pragma unroll
            for (int s = 0; s < 5; s++) {
                g_topD[(bx * N + row) * 5 + s] = t5d[r][s];
                g_topI[(bx * N + row) * 5 + s] = t5i[r][s];
            }
        }
    }
}

// ---------------------------------------------------------------------------
// Kernel C: merge CSPLIT partial top-5 lists, pick 5th-smallest, hinge term.
// ---------------------------------------------------------------------------
__global__ void finalize_kernel(const float* __restrict__ x, const float* __restrict__ p) {
    int row  = blockIdx.x * 8 + (threadIdx.x >> 5);
    int lane = threadIdx.x & 31;
    int neg = 0;
    if (lane == 0) {
        float ad[5], bd[5]; int ai[5], bi[5];
#pragma unroll
        for (int s = 0; s < 5; s++) {
            ad[s] = g_topD[(0 * N + row) * 5 + s]; ai[s] = g_topI[(0 * N + row) * 5 + s];
            bd[s] = g_topD[(1 * N + row) * 5 + s]; bi[s] = g_topI[(1 * N + row) * 5 + s];
        }
        int ia = 0, ib = 0;
#pragma unroll
        for (int s = 0; s < 5; s++) {
            bool ta = better(ad[ia], ai[ia], bd[ib], bi[ib]);
            neg = ta ? ai[ia] : bi[ib];
            if (ta) ia++; else ib++;
        }
    }
    neg = __shfl_sync(0xffffffffu, neg, 0);

    const float* xr = x + row * D;
    const float* pr = p + row * D;
    const float* nr = x + neg * D;
    float sap = 0.f, san = 0.f;
#pragma unroll
    for (int kk = 0; kk < 4; kk++) {
        int k = lane + 32 * kk;
        float xv = xr[k];
        float dp = xv - pr[k] + 1e-6f;
        float dn = xv - nr[k] + 1e-6f;
        sap = fmaf(dp, dp, sap);
        san = fmaf(dn, dn, san);
    }
#pragma unroll
    for (int o = 16; o; o >>= 1) {
        sap += __shfl_xor_sync(0xffffffffu, sap, o);
        san += __shfl_xor_sync(0xffffffffu, san, o);
    }
    if (lane == 0)
        g_hinge[row] = fmaxf(sqrtf(sap) - sqrtf(san) + 0.3f, 0.f);
}

// ---------------------------------------------------------------------------
// Kernel D: deterministic fixed-schedule mean
// ---------------------------------------------------------------------------
__global__ void reduce_kernel(float* out) {
    __shared__ float sh[256];
    int tid = threadIdx.x;
    float s = 0.f;
    for (int i = tid; i < N; i += 256) s += g_hinge[i];
    sh[tid] = s;
    __syncthreads();
    for (int o = 128; o; o >>= 1) {
        if (tid < o) sh[tid] += sh[tid + o];
        __syncthreads();
    }
    if (tid == 0) out[0] = sh[0] * (1.0f / N);
}

// ---------------------------------------------------------------------------
extern "C" void kernel_launch(void* const* d_in, const int* in_sizes, int n_in,
                              void* d_out, int out_size) {
    const float* x   = (const float*)d_in[0];
    const float* pos = (const float*)d_in[1];
    float* out = (float*)d_out;

    size_t smem_bytes = (size_t)(D * AST + D * BST) * sizeof(float);  // 100 KB
    cudaFuncSetAttribute(dist_top5_kernel,
                         cudaFuncAttributeMaxDynamicSharedMemorySize,
                         (int)smem_bytes);

    transpose_kernel<<<dim3(N / 32, D / 32), dim3(32, 8)>>>(x);
    sq_kernel<<<N / 8, 256>>>(x);
    dim3 grid(CSPLIT, N / RB);
    dist_top5_kernel<<<grid, 256, smem_bytes>>>();
    finalize_kernel<<<N / 8, 256>>>(x, pos);
    reduce_kernel<<<1, 256>>>(out);
}

// round 4
// speedup vs baseline: 1.8775x; 1.8775x over previous
#include <cuda_runtime.h>
#include <cuda_fp16.h>
#include <cstdint>

#define N 8192
#define D 128
#define KE 384                // expanded K: [hi|lo|hi] / [hi|hi|lo]
#define G 8                   // column groups (CTAs per row block)
#define MT 128                // rows per CTA
#define NTILE 128             // cols per tile
#define NTILES 8              // tiles per CTA
#define ASTRIDE 392           // A smem row stride in halfs (784B == 16 mod 128)
#define BSTRIDE 72            // B smem row stride in halfs (144B == 16 mod 128)
#define BBUF 18432            // 128*72*2 bytes per B buffer

// dynamic smem layout (bytes)
#define SM_SQC   0            // 128 floats
#define SM_A     512          // 128*392*2 = 100352
#define SM_B     100864       // 2 * 18432 = 36864
#define SM_SCRD  100864       // scratch (reuses B area at end): 128*5 floats
#define SM_SCRI  103424       // 128*5 ints
#define SM_TOTAL 137728

__device__ __half g_Ae[N * KE];
__device__ __half g_Be[N * KE];
__device__ float  g_sq[N];
__device__ float  g_topD[N * G * 5];
__device__ int    g_topI[N * G * 5];
__device__ float  g_hinge[N];

__device__ __forceinline__ bool better(float d1, int i1, float d2, int i2) {
    return (d1 < d2) || (d1 == d2 && i1 < i2);
}

__device__ __forceinline__ uint32_t smem_u32(const void* p) {
    uint32_t a;
    asm("{ .reg .u64 t; cvta.to.shared.u64 t, %1; cvt.u32.u64 %0, t; }" : "=r"(a) : "l"(p));
    return a;
}
__device__ __forceinline__ void ldsm_x4(uint32_t* r, uint32_t addr) {
    asm volatile("ldmatrix.sync.aligned.m8n8.x4.shared.b16 {%0,%1,%2,%3}, [%4];"
                 : "=r"(r[0]), "=r"(r[1]), "=r"(r[2]), "=r"(r[3]) : "r"(addr));
}
__device__ __forceinline__ void mma16816(float* d, const uint32_t* a, uint32_t b0, uint32_t b1) {
    asm volatile("mma.sync.aligned.m16n8k16.row.col.f32.f16.f16.f32 "
                 "{%0,%1,%2,%3}, {%4,%5,%6,%7}, {%8,%9}, {%0,%1,%2,%3};"
                 : "+f"(d[0]), "+f"(d[1]), "+f"(d[2]), "+f"(d[3])
                 : "r"(a[0]), "r"(a[1]), "r"(a[2]), "r"(a[3]), "r"(b0), "r"(b1));
}
__device__ __forceinline__ void cp_async16(uint32_t dst, const void* src) {
    asm volatile("cp.async.cg.shared.global [%0], [%1], 16;" :: "r"(dst), "l"(src));
}
__device__ __forceinline__ void cp_commit() {
    asm volatile("cp.async.commit_group;" ::: "memory");
}
__device__ __forceinline__ void cp_wait1() {
    asm volatile("cp.async.wait_group 1;" ::: "memory");
}
__device__ __forceinline__ void cp_wait0() {
    asm volatile("cp.async.wait_group 0;" ::: "memory");
}

// ---------------------------------------------------------------------------
// Kernel S: fp16 split expansion
// ---------------------------------------------------------------------------
__global__ void split_kernel(const float* __restrict__ x) {
    int idx = blockIdx.x * 256 + threadIdx.x;
    int row = idx >> 7, k = idx & 127;
    float f = x[idx];
    __half h = __float2half_rn(f);
    __half l = __float2half_rn(f - __half2float(h));
    __half* ae = g_Ae + row * KE;
    __half* be = g_Be + row * KE;
    ae[k] = h; ae[128 + k] = l; ae[256 + k] = h;
    be[k] = h; be[128 + k] = h; be[256 + k] = l;
}

// ---------------------------------------------------------------------------
// Kernel A: row squared norms (exact fp32)
// ---------------------------------------------------------------------------
__global__ void sq_kernel(const float* __restrict__ x) {
    int row  = blockIdx.x * 8 + (threadIdx.x >> 5);
    int lane = threadIdx.x & 31;
    const float* xr = x + row * D;
    float s = 0.f;
#pragma unroll
    for (int k = 0; k < 4; k++) {
        float v = xr[lane + 32 * k];
        s = fmaf(v, v, s);
    }
#pragma unroll
    for (int o = 16; o; o >>= 1) s += __shfl_xor_sync(0xffffffffu, s, o);
    if (lane == 0) g_sq[row] = s;
}

// ---------------------------------------------------------------------------
// Kernel B: mma.sync Gram tiles + fused per-row top-5.
// Grid (G, 64). 8 warps: wr = w>>1 (32-row group), wc = w&1 (64-col group).
// ---------------------------------------------------------------------------
__global__ __launch_bounds__(256, 1) void gram_top5_kernel() {
    extern __shared__ char sm[];
    float* sqc = (float*)(sm + SM_SQC);
    const uint32_t smBase = smem_u32(sm);
    const uint32_t smA = smBase + SM_A;
    const uint32_t smB = smBase + SM_B;

    const int tid = threadIdx.x;
    const int w = tid >> 5, l = tid & 31;
    const int wr = w >> 1, wc = w & 1;
    const int bx = blockIdx.x;
    const int rowBase = blockIdx.y * MT;

    // Resident A tile: 128 rows x 384 halfs (stride 392)
    {
        __half* As = (__half*)(sm + SM_A);
        for (int i = tid; i < 6144; i += 256) {
            int r = i / 48, c8 = i % 48;
            uint4 v = *(const uint4*)&g_Ae[(rowBase + r) * KE + c8 * 8];
            *(uint4*)&As[r * ASTRIDE + c8 * 8] = v;
        }
    }

    float sqR[4];
#pragma unroll
    for (int h = 0; h < 4; h++)
        sqR[h] = g_sq[rowBase + wr * 32 + (l >> 2) + h * 8];

    float t5d[4][5]; int t5i[4][5];
#pragma unroll
    for (int r = 0; r < 4; r++)
#pragma unroll
        for (int s = 0; s < 5; s++) { t5d[r][s] = __int_as_float(0x7f800000); t5i[r][s] = 0x7fffffff; }

    // per-lane ldmatrix address components
    const uint32_t aRow = smA + (uint32_t)((wr * 32 + (l & 15)) * (ASTRIDE * 2)) + ((l >> 4) & 1) * 16;
    const uint32_t bCol = smB + (uint32_t)((wc * 64 + (l & 7) + ((l >> 4) & 1) * 8) * (BSTRIDE * 2)) + ((l >> 3) & 1) * 16;

    __syncthreads();

    for (int u = 0; u < NTILES; u++) {
        const int colBase = (bx + u * G) * NTILE;

        if (tid < 128) sqc[tid] = g_sq[colBase + tid];

        // issue B chunks 0 and 1
#pragma unroll
        for (int cc = 0; cc < 2; cc++) {
#pragma unroll
            for (int v = 0; v < 4; v++) {
                int i = tid + v * 256;
                int col = i >> 3, k8 = i & 7;
                cp_async16(smB + cc * BBUF + (uint32_t)(col * (BSTRIDE * 2) + k8 * 16),
                           &g_Be[(colBase + col) * KE + cc * 64 + k8 * 8]);
            }
            cp_commit();
        }

        float acc[2][8][4];
#pragma unroll
        for (int mf = 0; mf < 2; mf++)
#pragma unroll
            for (int nf = 0; nf < 8; nf++)
#pragma unroll
                for (int q = 0; q < 4; q++) acc[mf][nf][q] = 0.f;

        for (int c = 0; c < 6; c++) {
            if (c < 5) cp_wait1(); else cp_wait0();
            __syncthreads();
            const uint32_t bbuf = bCol + (uint32_t)((c & 1) * BBUF);
            const uint32_t abase = aRow + (uint32_t)(c * 128);
#pragma unroll
            for (int ks = 0; ks < 4; ks++) {
                uint32_t a0[4], a1[4], b[4][4];
                ldsm_x4(a0, abase + ks * 32);
                ldsm_x4(a1, abase + 16 * (ASTRIDE * 2) + ks * 32);
#pragma unroll
                for (int nf4 = 0; nf4 < 4; nf4++)
                    ldsm_x4(b[nf4], bbuf + nf4 * 16 * (BSTRIDE * 2) + ks * 32);
#pragma unroll
                for (int nf = 0; nf < 8; nf++) {
                    uint32_t b0 = b[nf >> 1][(nf & 1) * 2];
                    uint32_t b1 = b[nf >> 1][(nf & 1) * 2 + 1];
                    mma16816(acc[0][nf], a0, b0, b1);
                    mma16816(acc[1][nf], a1, b0, b1);
                }
            }
            __syncthreads();
            if (c < 4) {
#pragma unroll
                for (int v = 0; v < 4; v++) {
                    int i = tid + v * 256;
                    int col = i >> 3, k8 = i & 7;
                    cp_async16(smB + (c & 1) * BBUF + (uint32_t)(col * (BSTRIDE * 2) + k8 * 16),
                               &g_Be[(colBase + col) * KE + (c + 2) * 64 + k8 * 8]);
                }
                cp_commit();
            }
        }

        // epilogue: insert candidates (cols ascending per row)
#pragma unroll
        for (int mf = 0; mf < 2; mf++)
#pragma unroll
            for (int h = 0; h < 2; h++) {
                const int rr = mf * 2 + h;
#pragma unroll
                for (int nf = 0; nf < 8; nf++)
#pragma unroll
                    for (int q = 0; q < 2; q++) {
                        int cloc = wc * 64 + nf * 8 + (l & 3) * 2 + q;
                        int j = colBase + cloc;
                        float dot = acc[mf][nf][h * 2 + q];
                        float d2 = fmaxf(fmaf(-2.f, dot, sqR[rr] + sqc[cloc]), 1e-12f);
                        if (better(d2, j, t5d[rr][4], t5i[rr][4])) {
                            float cd = d2; int ci = j;
#pragma unroll
                            for (int s = 0; s < 5; s++) {
                                if (better(cd, ci, t5d[rr][s], t5i[rr][s])) {
                                    float td = t5d[rr][s]; t5d[rr][s] = cd; cd = td;
                                    int   ti = t5i[rr][s]; t5i[rr][s] = ci; ci = ti;
                                }
                            }
                        }
                    }
            }
        __syncthreads();
    }

    // merge across the 4 lanes sharing each row (xor 1, 2 keeps l>>2 fixed)
#pragma unroll
    for (int rr = 0; rr < 4; rr++) {
#pragma unroll
        for (int off = 1; off < 4; off <<= 1) {
            float od[5]; int oi[5];
#pragma unroll
            for (int s = 0; s < 5; s++) {
                od[s] = __shfl_xor_sync(0xffffffffu, t5d[rr][s], off);
                oi[s] = __shfl_xor_sync(0xffffffffu, t5i[rr][s], off);
            }
            float ad[5]; int ai[5];
#pragma unroll
            for (int s = 0; s < 5; s++) { ad[s] = t5d[rr][s]; ai[s] = t5i[rr][s]; }
            int ia = 0, ib = 0;
#pragma unroll
            for (int s = 0; s < 5; s++) {
                bool ta = better(ad[ia], ai[ia], od[ib], oi[ib]);
                t5d[rr][s] = ta ? ad[ia] : od[ib];
                t5i[rr][s] = ta ? ai[ia] : oi[ib];
                if (ta) ia++; else ib++;
            }
        }
    }

    // cross-warp-col merge via smem scratch (reuses B area; all cp.async drained)
    float* scrD = (float*)(sm + SM_SCRD);
    int*   scrI = (int*)(sm + SM_SCRI);
    if (wc == 1 && (l & 3) == 0) {
#pragma unroll
        for (int rr = 0; rr < 4; rr++) {
            int rl = wr * 32 + (l >> 2) + (rr & 1) * 8 + (rr >> 1) * 16;
#pragma unroll
            for (int s = 0; s < 5; s++) { scrD[rl * 5 + s] = t5d[rr][s]; scrI[rl * 5 + s] = t5i[rr][s]; }
        }
    }
    __syncthreads();
    if (wc == 0 && (l & 3) == 0) {
#pragma unroll
        for (int rr = 0; rr < 4; rr++) {
            int rl = wr * 32 + (l >> 2) + (rr & 1) * 8 + (rr >> 1) * 16;
            float bd[5]; int bi[5];
#pragma unroll
            for (int s = 0; s < 5; s++) { bd[s] = scrD[rl * 5 + s]; bi[s] = scrI[rl * 5 + s]; }
            float rd[5]; int ri[5];
            int ia = 0, ib = 0;
#pragma unroll
            for (int s = 0; s < 5; s++) {
                bool ta = better(t5d[rr][ia], t5i[rr][ia], bd[ib], bi[ib]);
                rd[s] = ta ? t5d[rr][ia] : bd[ib];
                ri[s] = ta ? t5i[rr][ia] : bi[ib];
                if (ta) ia++; else ib++;
            }
            int row = rowBase + rl;
#pragma unroll
            for (int s = 0; s < 5; s++) {
                g_topD[(row * G + bx) * 5 + s] = rd[s];
                g_topI[(row * G + bx) * 5 + s] = ri[s];
            }
        }
    }
}

// ---------------------------------------------------------------------------
// Kernel C: merge G partial top-5 lists per row -> 5th NN, hinge term.
// ---------------------------------------------------------------------------
__global__ void finalize_kernel(const float* __restrict__ x, const float* __restrict__ p) {
    int row  = blockIdx.x * 8 + (threadIdx.x >> 5);
    int lane = threadIdx.x & 31;
    int neg = 0;
    if (lane == 0) {
        int pos[G];
#pragma unroll
        for (int q = 0; q < G; q++) pos[q] = 0;
#pragma unroll
        for (int s = 0; s < 5; s++) {
            float bd = __int_as_float(0x7f800000); int bi = 0x7fffffff, bl = 0;
#pragma unroll
            for (int q = 0; q < G; q++) {
                float dd = g_topD[(row * G + q) * 5 + pos[q]];
                int   ii = g_topI[(row * G + q) * 5 + pos[q]];
                if (better(dd, ii, bd, bi)) { bd = dd; bi = ii; bl = q; }
            }
            neg = bi; pos[bl]++;
        }
    }
    neg = __shfl_sync(0xffffffffu, neg, 0);

    const float* xr = x + row * D;
    const float* pr = p + row * D;
    const float* nr = x + neg * D;
    float sap = 0.f, san = 0.f;
#pragma unroll
    for (int kk = 0; kk < 4; kk++) {
        int k = lane + 32 * kk;
        float xv = xr[k];
        float dp = xv - pr[k] + 1e-6f;
        float dn = xv - nr[k] + 1e-6f;
        sap = fmaf(dp, dp, sap);
        san = fmaf(dn, dn, san);
    }
#pragma unroll
    for (int o = 16; o; o >>= 1) {
        sap += __shfl_xor_sync(0xffffffffu, sap, o);
        san += __shfl_xor_sync(0xffffffffu, san, o);
    }
    if (lane == 0)
        g_hinge[row] = fmaxf(sqrtf(sap) - sqrtf(san) + 0.3f, 0.f);
}

// ---------------------------------------------------------------------------
// Kernel D: deterministic fixed-schedule mean
// ---------------------------------------------------------------------------
__global__ void reduce_kernel(float* out) {
    __shared__ float sh[256];
    int tid = threadIdx.x;
    float s = 0.f;
    for (int i = tid; i < N; i += 256) s += g_hinge[i];
    sh[tid] = s;
    __syncthreads();
    for (int o = 128; o; o >>= 1) {
        if (tid < o) sh[tid] += sh[tid + o];
        __syncthreads();
    }
    if (tid == 0) out[0] = sh[0] * (1.0f / N);
}

// ---------------------------------------------------------------------------
extern "C" void kernel_launch(void* const* d_in, const int* in_sizes, int n_in,
                              void* d_out, int out_size) {
    const float* x   = (const float*)d_in[0];
    const float* pos = (const float*)d_in[1];
    float* out = (float*)d_out;

    cudaFuncSetAttribute(gram_top5_kernel,
                         cudaFuncAttributeMaxDynamicSharedMemorySize, SM_TOTAL);

    split_kernel<<<(N * D) / 256, 256>>>(x);
    sq_kernel<<<N / 8, 256>>>(x);
    gram_top5_kernel<<<dim3(G, N / MT), 256, SM_TOTAL>>>();
    finalize_kernel<<<N / 8, 256>>>(x, pos);
    reduce_kernel<<<1, 256>>>(out);
}

// round 5
// speedup vs baseline: 3.6608x; 1.9498x over previous
#include <cuda_runtime.h>
#include <cuda_fp16.h>
#include <cstdint>

#define N 8192
#define D 128
#define G 8                   // column stripes (CTAs per row block)
#define MT 128                // rows per CTA
#define NTILE 128             // cols per tile
#define NTILES 8              // tiles per CTA
#define TOPC 6                // candidate depth per stripe
#define STRH 136              // smem tile row stride in halfs (272B == 16 mod 128)
#define TBYTES 34816          // 128*136*2

// dynamic smem layout (bytes)
#define SM_SQC   0            // 2 * 128 floats = 1024
#define SM_A     1024         // 34816
#define SM_B     35840        // 2 * 34816 = 69632
#define SM_SCRM  35840        // scratch over B: 128*6 floats
#define SM_SCRI  38912        // 128*6 ints
#define SM_TOTAL 105472

__device__ __half g_xh[N * D];
__device__ float  g_sq[N];
__device__ int    g_topI[N * G * TOPC];
__device__ float  g_hinge[N];

__device__ __forceinline__ bool better(float d1, int i1, float d2, int i2) {
    return (d1 < d2) || (d1 == d2 && i1 < i2);
}
__device__ __forceinline__ uint32_t smem_u32(const void* p) {
    uint32_t a;
    asm("{ .reg .u64 t; cvta.to.shared.u64 t, %1; cvt.u32.u64 %0, t; }" : "=r"(a) : "l"(p));
    return a;
}
__device__ __forceinline__ void ldsm_x4(uint32_t* r, uint32_t addr) {
    asm volatile("ldmatrix.sync.aligned.m8n8.x4.shared.b16 {%0,%1,%2,%3}, [%4];"
                 : "=r"(r[0]), "=r"(r[1]), "=r"(r[2]), "=r"(r[3]) : "r"(addr));
}
__device__ __forceinline__ void mma16816(float* d, const uint32_t* a, uint32_t b0, uint32_t b1) {
    asm volatile("mma.sync.aligned.m16n8k16.row.col.f32.f16.f16.f32 "
                 "{%0,%1,%2,%3}, {%4,%5,%6,%7}, {%8,%9}, {%0,%1,%2,%3};"
                 : "+f"(d[0]), "+f"(d[1]), "+f"(d[2]), "+f"(d[3])
                 : "r"(a[0]), "r"(a[1]), "r"(a[2]), "r"(a[3]), "r"(b0), "r"(b1));
}
__device__ __forceinline__ void cp_async16(uint32_t dst, const void* src) {
    asm volatile("cp.async.cg.shared.global [%0], [%1], 16;" :: "r"(dst), "l"(src));
}
__device__ __forceinline__ void cp_commit() {
    asm volatile("cp.async.commit_group;" ::: "memory");
}
__device__ __forceinline__ void cp_wait1() {
    asm volatile("cp.async.wait_group 1;" ::: "memory");
}
__device__ __forceinline__ void cp_wait0() {
    asm volatile("cp.async.wait_group 0;" ::: "memory");
}

// depth-6 sorted insert, total order (d asc, idx asc)
__device__ __forceinline__ void ins6(float d, int i, float* td, int* ti) {
    if (better(d, i, td[TOPC - 1], ti[TOPC - 1])) {
        float cd = d; int ci = i;
#pragma unroll
        for (int s = 0; s < TOPC; s++) {
            if (better(cd, ci, td[s], ti[s])) {
                float t = td[s]; td[s] = cd; cd = t;
                int   u = ti[s]; ti[s] = ci; ci = u;
            }
        }
    }
}

// ---------------------------------------------------------------------------
// Kernel S: fp16 cast
// ---------------------------------------------------------------------------
__global__ void split_kernel(const float* __restrict__ x) {
    int idx = blockIdx.x * 256 + threadIdx.x;
    g_xh[idx] = __float2half_rn(x[idx]);
}

// ---------------------------------------------------------------------------
// Kernel A: exact row squared norms
// ---------------------------------------------------------------------------
__global__ void sq_kernel(const float* __restrict__ x) {
    int row  = blockIdx.x * 8 + (threadIdx.x >> 5);
    int lane = threadIdx.x & 31;
    const float* xr = x + row * D;
    float s = 0.f;
#pragma unroll
    for (int k = 0; k < 4; k++) {
        float v = xr[lane + 32 * k];
        s = fmaf(v, v, s);
    }
#pragma unroll
    for (int o = 16; o; o >>= 1) s += __shfl_xor_sync(0xffffffffu, s, o);
    if (lane == 0) g_sq[row] = s;
}

// ---------------------------------------------------------------------------
// Kernel B: approx fp16 Gram + per-row top-6 candidates per stripe.
// Grid (G, 64), 512 threads = 16 warps: wr = w>>1 (16-row group), wc = w&1
// (64-col group). Rank key m = sq_j - 2*dot (row term rank-invariant).
// ---------------------------------------------------------------------------
__global__ __launch_bounds__(512, 1) void gram_top_kernel() {
    extern __shared__ char sm[];
    float* sqc = (float*)(sm + SM_SQC);
    const uint32_t smBase = smem_u32(sm);
    const uint32_t smA = smBase + SM_A;
    const uint32_t smB = smBase + SM_B;

    const int tid = threadIdx.x;
    const int w = tid >> 5, l = tid & 31;
    const int wr = w >> 1, wc = w & 1;
    const int bx = blockIdx.x;
    const int rowBase = blockIdx.y * MT;

    // resident A tile: 128 rows x 128 halfs, stride 136
    {
        const __half* Ag = g_xh + rowBase * D;
        for (int i = tid; i < 2048; i += 512) {
            int r = i >> 4, c8 = i & 15;
            uint4 v = *(const uint4*)(Ag + r * D + c8 * 8);
            *(uint4*)(sm + SM_A + r * (STRH * 2) + c8 * 16) = v;
        }
    }

    // prologue: B(0) + sqc(0)
    {
        const int cb = bx * NTILE;
#pragma unroll
        for (int v = 0; v < 4; v++) {
            int i = tid + v * 512;
            int col = i >> 4, k8 = i & 15;
            cp_async16(smB + (uint32_t)(col * (STRH * 2) + k8 * 16),
                       g_xh + (cb + col) * D + k8 * 8);
        }
        cp_commit();
        if (tid < 128) sqc[tid] = g_sq[cb + tid];
    }

    float md[2][TOPC]; int mi[2][TOPC];
#pragma unroll
    for (int h = 0; h < 2; h++)
#pragma unroll
        for (int s = 0; s < TOPC; s++) { md[h][s] = __int_as_float(0x7f800000); mi[h][s] = 0x7fffffff; }

    const uint32_t aBase = smA + (uint32_t)((wr * 16 + (l & 15)) * (STRH * 2)) + ((l >> 4) & 1) * 16;
    const uint32_t bOff  = (uint32_t)((wc * 64 + (l & 7) + ((l >> 4) & 1) * 8) * (STRH * 2)) + ((l >> 3) & 1) * 16;

    for (int u = 0; u < NTILES; u++) {
        const int colBase = (bx + u * G) * NTILE;

        if (u < NTILES - 1) {
            const int cb1 = (bx + (u + 1) * G) * NTILE;
            const uint32_t dstB = smB + (uint32_t)(((u + 1) & 1) * TBYTES);
#pragma unroll
            for (int v = 0; v < 4; v++) {
                int i = tid + v * 512;
                int col = i >> 4, k8 = i & 15;
                cp_async16(dstB + (uint32_t)(col * (STRH * 2) + k8 * 16),
                           g_xh + (cb1 + col) * D + k8 * 8);
            }
            cp_commit();
            if (tid < 128) sqc[((u + 1) & 1) * 128 + tid] = g_sq[cb1 + tid];
            cp_wait1();
        } else {
            cp_wait0();
        }
        __syncthreads();

        float acc[8][4];
#pragma unroll
        for (int nf = 0; nf < 8; nf++)
#pragma unroll
            for (int q = 0; q < 4; q++) acc[nf][q] = 0.f;

        const uint32_t bBase = smB + (uint32_t)((u & 1) * TBYTES) + bOff;
#pragma unroll
        for (int ks = 0; ks < 8; ks++) {
            uint32_t a[4], b[4][4];
            ldsm_x4(a, aBase + ks * 32);
#pragma unroll
            for (int nf4 = 0; nf4 < 4; nf4++)
                ldsm_x4(b[nf4], bBase + nf4 * 16 * (STRH * 2) + ks * 32);
#pragma unroll
            for (int nf = 0; nf < 8; nf++)
                mma16816(acc[nf], a, b[nf >> 1][(nf & 1) * 2], b[nf >> 1][(nf & 1) * 2 + 1]);
        }

        const float* sq = sqc + (u & 1) * 128;
#pragma unroll
        for (int h = 0; h < 2; h++)
#pragma unroll
            for (int nf = 0; nf < 8; nf++)
#pragma unroll
                for (int q = 0; q < 2; q++) {
                    int cloc = wc * 64 + nf * 8 + (l & 3) * 2 + q;
                    float m = fmaf(-2.f, acc[nf][h * 2 + q], sq[cloc]);
                    ins6(m, colBase + cloc, md[h], mi[h]);
                }
        __syncthreads();
    }

    // merge across 4 lanes sharing each row (xor 1,2 varies l&3 only)
#pragma unroll
    for (int h = 0; h < 2; h++) {
#pragma unroll
        for (int off = 1; off < 4; off <<= 1) {
            float od[TOPC]; int oi[TOPC];
#pragma unroll
            for (int s = 0; s < TOPC; s++) {
                od[s] = __shfl_xor_sync(0xffffffffu, md[h][s], off);
                oi[s] = __shfl_xor_sync(0xffffffffu, mi[h][s], off);
            }
            float ad[TOPC]; int ai[TOPC];
#pragma unroll
            for (int s = 0; s < TOPC; s++) { ad[s] = md[h][s]; ai[s] = mi[h][s]; }
            int ia = 0, ib = 0;
#pragma unroll
            for (int s = 0; s < TOPC; s++) {
                bool ta = better(ad[ia], ai[ia], od[ib], oi[ib]);
                md[h][s] = ta ? ad[ia] : od[ib];
                mi[h][s] = ta ? ai[ia] : oi[ib];
                if (ta) ia++; else ib++;
            }
        }
    }

    // cross-wc merge via smem scratch (B dead)
    float* scrM = (float*)(sm + SM_SCRM);
    int*   scrI = (int*)(sm + SM_SCRI);
    if (wc == 1 && (l & 3) == 0) {
#pragma unroll
        for (int h = 0; h < 2; h++) {
            int rl = wr * 16 + (l >> 2) + h * 8;
#pragma unroll
            for (int s = 0; s < TOPC; s++) { scrM[rl * TOPC + s] = md[h][s]; scrI[rl * TOPC + s] = mi[h][s]; }
        }
    }
    __syncthreads();
    if (wc == 0 && (l & 3) == 0) {
#pragma unroll
        for (int h = 0; h < 2; h++) {
            int rl = wr * 16 + (l >> 2) + h * 8;
            float bd[TOPC]; int bi[TOPC];
#pragma unroll
            for (int s = 0; s < TOPC; s++) { bd[s] = scrM[rl * TOPC + s]; bi[s] = scrI[rl * TOPC + s]; }
            int ia = 0, ib = 0;
            int row = rowBase + rl;
#pragma unroll
            for (int s = 0; s < TOPC; s++) {
                bool ta = better(md[h][ia], mi[h][ia], bd[ib], bi[ib]);
                g_topI[(row * G + bx) * TOPC + s] = ta ? mi[h][ia] : bi[ib];
                if (ta) ia++; else ib++;
            }
        }
    }
}

// ---------------------------------------------------------------------------
// Kernel C: exact rescoring of 48 candidates -> true 5th NN -> hinge.
// One warp per row.
// ---------------------------------------------------------------------------
__global__ void finalize_kernel(const float* __restrict__ x, const float* __restrict__ p) {
    int row  = blockIdx.x * 8 + (threadIdx.x >> 5);
    int lane = threadIdx.x & 31;

    float4 xi = ((const float4*)(x + row * D))[lane];

    float t5d[5]; int t5i[5];
#pragma unroll
    for (int s = 0; s < 5; s++) { t5d[s] = __int_as_float(0x7f800000); t5i[s] = 0x7fffffff; }

    const int* cand = g_topI + row * G * TOPC;
    for (int c = 0; c < G * TOPC; c++) {
        int j = cand[c];
        float4 xj = ((const float4*)(x + j * D))[lane];
        float d0 = xi.x - xj.x, d1 = xi.y - xj.y, d2_ = xi.z - xj.z, d3 = xi.w - xj.w;
        float s = fmaf(d0, d0, fmaf(d1, d1, fmaf(d2_, d2_, d3 * d3)));
#pragma unroll
        for (int o = 16; o; o >>= 1) s += __shfl_xor_sync(0xffffffffu, s, o);
        float d2 = fmaxf(s, 1e-12f);
        // uniform across warp -> no divergence
        if (better(d2, j, t5d[4], t5i[4])) {
            float cd = d2; int ci = j;
#pragma unroll
            for (int k = 0; k < 5; k++) {
                if (better(cd, ci, t5d[k], t5i[k])) {
                    float td = t5d[k]; t5d[k] = cd; cd = td;
                    int   ti = t5i[k]; t5i[k] = ci; ci = ti;
                }
            }
        }
    }
    int neg = t5i[4];

    float4 pi = ((const float4*)(p + row * D))[lane];
    float4 xn = ((const float4*)(x + neg * D))[lane];
    float ap0 = xi.x - pi.x + 1e-6f, ap1 = xi.y - pi.y + 1e-6f;
    float ap2 = xi.z - pi.z + 1e-6f, ap3 = xi.w - pi.w + 1e-6f;
    float an0 = xi.x - xn.x + 1e-6f, an1 = xi.y - xn.y + 1e-6f;
    float an2 = xi.z - xn.z + 1e-6f, an3 = xi.w - xn.w + 1e-6f;
    float sap = fmaf(ap0, ap0, fmaf(ap1, ap1, fmaf(ap2, ap2, ap3 * ap3)));
    float san = fmaf(an0, an0, fmaf(an1, an1, fmaf(an2, an2, an3 * an3)));
#pragma unroll
    for (int o = 16; o; o >>= 1) {
        sap += __shfl_xor_sync(0xffffffffu, sap, o);
        san += __shfl_xor_sync(0xffffffffu, san, o);
    }
    if (lane == 0)
        g_hinge[row] = fmaxf(sqrtf(sap) - sqrtf(san) + 0.3f, 0.f);
}

// ---------------------------------------------------------------------------
// Kernel D: deterministic fixed-schedule mean
// ---------------------------------------------------------------------------
__global__ void reduce_kernel(float* out) {
    __shared__ float sh[256];
    int tid = threadIdx.x;
    float s = 0.f;
    for (int i = tid; i < N; i += 256) s += g_hinge[i];
    sh[tid] = s;
    __syncthreads();
    for (int o = 128; o; o >>= 1) {
        if (tid < o) sh[tid] += sh[tid + o];
        __syncthreads();
    }
    if (tid == 0) out[0] = sh[0] * (1.0f / N);
}

// ---------------------------------------------------------------------------
extern "C" void kernel_launch(void* const* d_in, const int* in_sizes, int n_in,
                              void* d_out, int out_size) {
    const float* x   = (const float*)d_in[0];
    const float* pos = (const float*)d_in[1];
    float* out = (float*)d_out;

    cudaFuncSetAttribute(gram_top_kernel,
                         cudaFuncAttributeMaxDynamicSharedMemorySize, SM_TOTAL);

    split_kernel<<<(N * D) / 256, 256>>>(x);
    sq_kernel<<<N / 8, 256>>>(x);
    gram_top_kernel<<<dim3(G, N / MT), 512, SM_TOTAL>>>();
    finalize_kernel<<<N / 8, 256>>>(x, pos);
    reduce_kernel<<<1, 256>>>(out);
}

// round 6
// speedup vs baseline: 12.3158x; 3.3643x over previous
#include <cuda_runtime.h>
#include <cuda_fp16.h>
#include <cstdint>

#define N 8192
#define D 128
#define G 8                   // column stripes
#define MT 64                 // rows per CTA
#define NTILE 128             // cols per tile
#define NTILES 8              // tiles per CTA
#define KEEP 5                // output candidates per (row, stripe)
#define STRH 136              // smem tile row stride in halfs (272B)
#define TBYTES 34816          // 128*136*2

// dynamic smem layout (bytes)
#define SM_SQC   0            // 2 * 128 floats = 1024
#define SM_A     1024         // 64*272 = 17408
#define SM_B     18432        // 2 * 34816 = 69632
#define SM_SCR   1024         // scratch over A after tile loop: 64*5 uints
#define SM_TOTAL 88064

__device__ __half g_xh[N * D];
__device__ float  g_sq[N];
__device__ int    g_topI[N * G * KEEP];
__device__ float  g_hinge[N];

__device__ __forceinline__ bool better(float d1, int i1, float d2, int i2) {
    return (d1 < d2) || (d1 == d2 && i1 < i2);
}
__device__ __forceinline__ uint32_t smem_u32(const void* p) {
    uint32_t a;
    asm("{ .reg .u64 t; cvta.to.shared.u64 t, %1; cvt.u32.u64 %0, t; }" : "=r"(a) : "l"(p));
    return a;
}
__device__ __forceinline__ void ldsm_x4(uint32_t* r, uint32_t addr) {
    asm volatile("ldmatrix.sync.aligned.m8n8.x4.shared.b16 {%0,%1,%2,%3}, [%4];"
                 : "=r"(r[0]), "=r"(r[1]), "=r"(r[2]), "=r"(r[3]) : "r"(addr));
}
__device__ __forceinline__ void mma16816(float* d, const uint32_t* a, uint32_t b0, uint32_t b1) {
    asm volatile("mma.sync.aligned.m16n8k16.row.col.f32.f16.f16.f32 "
                 "{%0,%1,%2,%3}, {%4,%5,%6,%7}, {%8,%9}, {%0,%1,%2,%3};"
                 : "+f"(d[0]), "+f"(d[1]), "+f"(d[2]), "+f"(d[3])
                 : "r"(a[0]), "r"(a[1]), "r"(a[2]), "r"(a[3]), "r"(b0), "r"(b1));
}
__device__ __forceinline__ void cp_async16(uint32_t dst, const void* src) {
    asm volatile("cp.async.cg.shared.global [%0], [%1], 16;" :: "r"(dst), "l"(src));
}
__device__ __forceinline__ void cp_commit() { asm volatile("cp.async.commit_group;" ::: "memory"); }
__device__ __forceinline__ void cp_wait1() { asm volatile("cp.async.wait_group 1;" ::: "memory"); }
__device__ __forceinline__ void cp_wait0() { asm volatile("cp.async.wait_group 0;" ::: "memory"); }

// branchless depth-4 sorted insert on uint keys (8 IMNMX)
__device__ __forceinline__ void ins4(uint32_t c, uint32_t* t) {
#pragma unroll
    for (int s = 0; s < 4; s++) {
        uint32_t lo = min(t[s], c);
        c = max(t[s], c);
        t[s] = lo;
    }
}
// branchless insert into sorted-5 keep-5 (10 IMNMX)
__device__ __forceinline__ void ins5(uint32_t c, uint32_t* t) {
#pragma unroll
    for (int s = 0; s < 5; s++) {
        uint32_t lo = min(t[s], c);
        c = max(t[s], c);
        t[s] = lo;
    }
}

// ---------------------------------------------------------------------------
// Kernel P: fused fp16 cast + exact row norms
// ---------------------------------------------------------------------------
__global__ void prep_kernel(const float* __restrict__ x) {
    int row  = blockIdx.x * 8 + (threadIdx.x >> 5);
    int lane = threadIdx.x & 31;
    const float* xr = x + row * D;
    float s = 0.f;
#pragma unroll
    for (int kk = 0; kk < 4; kk++) {
        int k = lane + 32 * kk;
        float v = xr[k];
        g_xh[row * D + k] = __float2half_rn(v);
        s = fmaf(v, v, s);
    }
#pragma unroll
    for (int o = 16; o; o >>= 1) s += __shfl_xor_sync(0xffffffffu, s, o);
    if (lane == 0) g_sq[row] = s;
}

// ---------------------------------------------------------------------------
// Kernel B: approx fp16 Gram + branchless per-row candidate selection.
// Grid (G, 128), 256 threads = 8 warps: wr = w>>1 (16-row group), wc = w&1
// (64-col group). Candidate key = quantized(d^2+1) | id9.
// ---------------------------------------------------------------------------
__global__ __launch_bounds__(256, 2) void gram_top_kernel() {
    extern __shared__ char sm[];
    float* sqcP = (float*)(sm + SM_SQC);
    const uint32_t smBase = smem_u32(sm);
    const uint32_t smA = smBase + SM_A;
    const uint32_t smB = smBase + SM_B;

    const int tid = threadIdx.x;
    const int w = tid >> 5, l = tid & 31;
    const int wr = w >> 1, wc = w & 1;
    const int lane2 = l & 3;
    const int bx = blockIdx.x;
    const int rowBase = blockIdx.y * MT;

    // resident A tile: 64 rows x 128 halfs, stride 136
    {
        const __half* Ag = g_xh + rowBase * D;
#pragma unroll
        for (int v = 0; v < 4; v++) {
            int i = tid + v * 256;
            int r = i >> 4, c8 = i & 15;
            uint4 val = *(const uint4*)(Ag + r * D + c8 * 8);
            *(uint4*)(sm + SM_A + r * (STRH * 2) + c8 * 16) = val;
        }
    }

    // prologue: B(0) + sqcP(0)
    {
#pragma unroll
        for (int v = 0; v < 8; v++) {
            int i = tid + v * 256;
            int col = i >> 4, k8 = i & 15;
            cp_async16(smB + (uint32_t)(col * (STRH * 2) + k8 * 16),
                       g_xh + (bx * NTILE + col) * D + k8 * 8);
        }
        cp_commit();
        if (tid < 128) sqcP[tid] = g_sq[bx * NTILE + tid] + 1.0f;
    }

    float sqR[2];
    sqR[0] = g_sq[rowBase + wr * 16 + (l >> 2)];
    sqR[1] = g_sq[rowBase + wr * 16 + (l >> 2) + 8];

    uint32_t kd[2][4];
#pragma unroll
    for (int h = 0; h < 2; h++)
#pragma unroll
        for (int s = 0; s < 4; s++) kd[h][s] = 0xFFFFFFFFu;

    const uint32_t aBase = smA + (uint32_t)((wr * 16 + (l & 15)) * (STRH * 2)) + ((l >> 4) & 1) * 16;
    const uint32_t bOff  = (uint32_t)((wc * 64 + (l & 7) + ((l >> 4) & 1) * 8) * (STRH * 2)) + ((l >> 3) & 1) * 16;

    float rsq = 0.f;
    for (int u = 0; u < NTILES; u++) {
        if (u < NTILES - 1) {
            const int cb1 = (bx + (u + 1) * G) * NTILE;
            const uint32_t dstB = smB + (uint32_t)(((u + 1) & 1) * TBYTES);
#pragma unroll
            for (int v = 0; v < 8; v++) {
                int i = tid + v * 256;
                int col = i >> 4, k8 = i & 15;
                cp_async16(dstB + (uint32_t)(col * (STRH * 2) + k8 * 16),
                           g_xh + (cb1 + col) * D + k8 * 8);
            }
            cp_commit();
            if (tid < 128) rsq = g_sq[cb1 + tid] + 1.0f;   // LDG hidden by MMA below
            cp_wait1();
        } else {
            cp_wait0();
        }
        __syncthreads();

        float acc[8][4];
#pragma unroll
        for (int nf = 0; nf < 8; nf++)
#pragma unroll
            for (int q = 0; q < 4; q++) acc[nf][q] = 0.f;

        const uint32_t bBase = smB + (uint32_t)((u & 1) * TBYTES) + bOff;
#pragma unroll
        for (int ks = 0; ks < 8; ks++) {
            uint32_t a[4], b[4][4];
            ldsm_x4(a, aBase + ks * 32);
#pragma unroll
            for (int nf4 = 0; nf4 < 4; nf4++)
                ldsm_x4(b[nf4], bBase + nf4 * 16 * (STRH * 2) + ks * 32);
#pragma unroll
            for (int nf = 0; nf < 8; nf++)
                mma16816(acc[nf], a, b[nf >> 1][(nf & 1) * 2], b[nf >> 1][(nf & 1) * 2 + 1]);
        }

        // branchless epilogue
        const float* sq = sqcP + (u & 1) * 128;
        const uint32_t idb = ((uint32_t)u << 6) | (uint32_t)lane2;
#pragma unroll
        for (int nf = 0; nf < 8; nf++)
#pragma unroll
            for (int q = 0; q < 2; q++) {
                int cloc = wc * 64 + nf * 8 + lane2 * 2 + q;
                float sj = sq[cloc];
#pragma unroll
                for (int h = 0; h < 2; h++) {
                    float kf = fmaxf(fmaf(-2.f, acc[nf][h * 2 + q], sqR[h] + sj), 1.0f);
                    uint32_t key = (__float_as_uint(kf) & 0xFFFFFE00u) |
                                   idb | (uint32_t)((nf << 3) | (q << 2));
                    ins4(key, kd[h]);
                }
            }

        if (u < NTILES - 1 && tid < 128) sqcP[((u + 1) & 1) * 128 + tid] = rsq;
        __syncthreads();
    }

    // merge across the 4 lanes of each quad (keys identical comparator)
    uint32_t t5[2][5];
#pragma unroll
    for (int h = 0; h < 2; h++) {
#pragma unroll
        for (int s = 0; s < 4; s++) t5[h][s] = kd[h][s];
        t5[h][4] = 0xFFFFFFFFu;
        // xor 1: exchange the original 4-lists
#pragma unroll
        for (int s = 0; s < 4; s++)
            ins5(__shfl_xor_sync(0xffffffffu, kd[h][s], 1), t5[h]);
        // xor 2: exchange merged 5-lists
        uint32_t o[5];
#pragma unroll
        for (int s = 0; s < 5; s++) o[s] = __shfl_xor_sync(0xffffffffu, t5[h][s], 2);
#pragma unroll
        for (int s = 0; s < 5; s++) ins5(o[s], t5[h]);
    }

    // cross-wc merge: wc==1 publishes keys, wc==0 decodes + merges + writes
    uint32_t* scr = (uint32_t*)(sm + SM_SCR);
    __syncthreads();   // A reads done; scratch safe
    if (wc == 1 && lane2 == 0) {
#pragma unroll
        for (int h = 0; h < 2; h++) {
            int rl = wr * 16 + (l >> 2) + h * 8;
#pragma unroll
            for (int s = 0; s < 5; s++) scr[rl * 5 + s] = t5[h][s];
        }
    }
    __syncthreads();
    if (wc == 0 && lane2 == 0) {
#pragma unroll
        for (int h = 0; h < 2; h++) {
            int rl = wr * 16 + (l >> 2) + h * 8;
            // decode own (wc=0)
            uint32_t rk[5]; int rj[5];
#pragma unroll
            for (int s = 0; s < 5; s++) {
                uint32_t id = t5[h][s] & 0x1FFu;
                rk[s] = t5[h][s];
                rj[s] = bx * NTILE + (int)(id >> 6) * (G * NTILE) +
                        (int)((id >> 3) & 7) * 8 + (int)(id & 3) * 2 + (int)((id >> 2) & 1);
            }
            // insert other's 5 (wc=1)
#pragma unroll
            for (int e = 0; e < 5; e++) {
                uint32_t ck = scr[rl * 5 + e];
                uint32_t id = ck & 0x1FFu;
                int cj = bx * NTILE + (int)(id >> 6) * (G * NTILE) + 64 +
                         (int)((id >> 3) & 7) * 8 + (int)(id & 3) * 2 + (int)((id >> 2) & 1);
#pragma unroll
                for (int s = 0; s < 5; s++) {
                    bool lt = ck < rk[s];
                    uint32_t nk = lt ? ck : rk[s];
                    int      nj = lt ? cj : rj[s];
                    ck = lt ? rk[s] : ck;
                    cj = lt ? rj[s] : cj;
                    rk[s] = nk; rj[s] = nj;
                }
            }
            int row = rowBase + rl;
#pragma unroll
            for (int s = 0; s < 5; s++)
                g_topI[(row * G + bx) * KEEP + s] = rj[s];
        }
    }
}

// ---------------------------------------------------------------------------
// Kernel C: exact rescoring of 40 candidates -> true 5th NN -> hinge.
// ---------------------------------------------------------------------------
__global__ void finalize_kernel(const float* __restrict__ x, const float* __restrict__ p) {
    int row  = blockIdx.x * 8 + (threadIdx.x >> 5);
    int lane = threadIdx.x & 31;

    float4 xi = ((const float4*)(x + row * D))[lane];

    float t5d[5]; int t5i[5];
#pragma unroll
    for (int s = 0; s < 5; s++) { t5d[s] = __int_as_float(0x7f800000); t5i[s] = 0x7fffffff; }

    const int* cand = g_topI + row * G * KEEP;
    for (int c = 0; c < G * KEEP; c++) {
        int j = cand[c];
        float4 xj = ((const float4*)(x + j * D))[lane];
        float d0 = xi.x - xj.x, d1 = xi.y - xj.y, d2_ = xi.z - xj.z, d3 = xi.w - xj.w;
        float s = fmaf(d0, d0, fmaf(d1, d1, fmaf(d2_, d2_, d3 * d3)));
#pragma unroll
        for (int o = 16; o; o >>= 1) s += __shfl_xor_sync(0xffffffffu, s, o);
        float d2 = fmaxf(s, 1e-12f);
        if (better(d2, j, t5d[4], t5i[4])) {
            float cd = d2; int ci = j;
#pragma unroll
            for (int k = 0; k < 5; k++) {
                if (better(cd, ci, t5d[k], t5i[k])) {
                    float td = t5d[k]; t5d[k] = cd; cd = td;
                    int   ti = t5i[k]; t5i[k] = ci; ci = ti;
                }
            }
        }
    }
    int neg = t5i[4];

    float4 pi = ((const float4*)(p + row * D))[lane];
    float4 xn = ((const float4*)(x + neg * D))[lane];
    float ap0 = xi.x - pi.x + 1e-6f, ap1 = xi.y - pi.y + 1e-6f;
    float ap2 = xi.z - pi.z + 1e-6f, ap3 = xi.w - pi.w + 1e-6f;
    float an0 = xi.x - xn.x + 1e-6f, an1 = xi.y - xn.y + 1e-6f;
    float an2 = xi.z - xn.z + 1e-6f, an3 = xi.w - xn.w + 1e-6f;
    float sap = fmaf(ap0, ap0, fmaf(ap1, ap1, fmaf(ap2, ap2, ap3 * ap3)));
    float san = fmaf(an0, an0, fmaf(an1, an1, fmaf(an2, an2, an3 * an3)));
#pragma unroll
    for (int o = 16; o; o >>= 1) {
        sap += __shfl_xor_sync(0xffffffffu, sap, o);
        san += __shfl_xor_sync(0xffffffffu, san, o);
    }
    if (lane == 0)
        g_hinge[row] = fmaxf(sqrtf(sap) - sqrtf(san) + 0.3f, 0.f);
}

// ---------------------------------------------------------------------------
// Kernel D: deterministic fixed-schedule mean
// ---------------------------------------------------------------------------
__global__ void reduce_kernel(float* out) {
    __shared__ float sh[256];
    int tid = threadIdx.x;
    float s = 0.f;
    for (int i = tid; i < N; i += 256) s += g_hinge[i];
    sh[tid] = s;
    __syncthreads();
    for (int o = 128; o; o >>= 1) {
        if (tid < o) sh[tid] += sh[tid + o];
        __syncthreads();
    }
    if (tid == 0) out[0] = sh[0] * (1.0f / N);
}

// ---------------------------------------------------------------------------
extern "C" void kernel_launch(void* const* d_in, const int* in_sizes, int n_in,
                              void* d_out, int out_size) {
    const float* x   = (const float*)d_in[0];
    const float* pos = (const float*)d_in[1];
    float* out = (float*)d_out;

    cudaFuncSetAttribute(gram_top_kernel,
                         cudaFuncAttributeMaxDynamicSharedMemorySize, SM_TOTAL);

    prep_kernel<<<N / 8, 256>>>(x);
    gram_top_kernel<<<dim3(G, N / MT), 256, SM_TOTAL>>>();
    finalize_kernel<<<N / 8, 256>>>(x, pos);
    reduce_kernel<<<1, 256>>>(out);
}